// round 13
// baseline (speedup 1.0000x reference)
#include <cuda_runtime.h>
#include <cuda_bf16.h>
#include <cstdint>

#define NB 8
#define NC 256
#define ND 128
#define NN 4096   // 64*64

// ---------------- scratch (static device globals; no allocation) ----------------
__device__ __nv_bfloat16 g_qpT[(size_t)NB * ND * NN];     // 8 MB [b][d][n], pre-scaled 1/sqrt(D)
__device__ __nv_bfloat16 g_kpT[(size_t)NB * ND * NN];     // 8 MB [b][d][m]
__device__ __nv_bfloat16 g_vpT[(size_t)NB * ND * NN];     // 8 MB [b][d][m]; later *= 1/sum[m]
__device__ __nv_bfloat16 g_avh[(size_t)NB * NN * ND];     // 8 MB attention out [b][n][d]
__device__ __nv_bfloat16 g_E[(size_t)NB * NN * NN];       // 268 MB E = exp(S) [b][n][m]
__device__ float         g_sum[NB * NN];                  // column sums of E over n

// ---------------- fast exp (FFMA-only) -------------------------------------------
__device__ __forceinline__ float fexp(float x) {
    x = fmaxf(x, -30.0f);
    float t  = fmaf(x, 1.4426950408889634f, 12582912.0f);
    int   i  = __float_as_int(t);
    float fi = t - 12582912.0f;
    float f  = fmaf(x, 1.4426950408889634f, -fi);
    float p  = 9.6181291e-3f;
    p = fmaf(p, f, 5.5504109e-2f);
    p = fmaf(p, f, 2.4022651e-1f);
    p = fmaf(p, f, 6.9314718e-1f);
    p = fmaf(p, f, 1.0f);
    return __int_as_float(__float_as_int(p) + (i << 23));
}
__device__ __forceinline__ uint32_t pack_bf2(float a, float b) {
    __nv_bfloat162 h = __floats2bfloat162_rn(a, b);
    return *reinterpret_cast<uint32_t*>(&h);
}

// ---------------- HMMA + ldmatrix + cp.async helpers -----------------------------
__device__ __forceinline__ void mma16816(float* d,
                                         uint32_t a0, uint32_t a1, uint32_t a2, uint32_t a3,
                                         uint32_t b0, uint32_t b1) {
    asm volatile(
        "mma.sync.aligned.m16n8k16.row.col.f32.bf16.bf16.f32 "
        "{%0,%1,%2,%3}, {%4,%5,%6,%7}, {%8,%9}, {%0,%1,%2,%3};"
        : "+f"(d[0]), "+f"(d[1]), "+f"(d[2]), "+f"(d[3])
        : "r"(a0), "r"(a1), "r"(a2), "r"(a3), "r"(b0), "r"(b1));
}
__device__ __forceinline__ void ldsm4t(uint32_t addr, uint32_t* r) {
    asm volatile("ldmatrix.sync.aligned.m8n8.x4.trans.shared.b16 {%0,%1,%2,%3}, [%4];"
                 : "=r"(r[0]), "=r"(r[1]), "=r"(r[2]), "=r"(r[3]) : "r"(addr));
}
__device__ __forceinline__ void ldsm4(uint32_t addr, uint32_t* r) {
    asm volatile("ldmatrix.sync.aligned.m8n8.x4.shared.b16 {%0,%1,%2,%3}, [%4];"
                 : "=r"(r[0]), "=r"(r[1]), "=r"(r[2]), "=r"(r[3]) : "r"(addr));
}
__device__ __forceinline__ void cpa16(uint32_t dst, const void* src) {
    asm volatile("cp.async.cg.shared.global [%0], [%1], 16;" :: "r"(dst), "l"(src) : "memory");
}
#define CP_COMMIT() asm volatile("cp.async.commit_group;" ::: "memory")
#define CP_WAIT(n)  asm volatile("cp.async.wait_group %0;" :: "n"(n) : "memory")
__device__ __forceinline__ uint32_t smem_u32(const void* p) {
    return (uint32_t)__cvta_generic_to_shared(p);
}

// smem row strides (words): 128 bf16 + 8 pad = 68 words (bank shift 4 per row)
#define KW128 68
#define TILE128 (128 * KW128)     // 8704 words = 34816 B
// 64-col rows: 32 + 4 pad = 36 words (144 B)
#define KW64 36

// pv64 smem: stage = A(64 rows x 144B = 9216) + B(128 rows x 144B = 18432) = 27648 B
#define PV_STAGE   27648
#define PV_SMEM    (2 * PV_STAGE)     // 55296 B -> 3 CTAs/SM

// ================================================================================
// K1: projections -> TRANSPOSED outputs [d][n].  (R8, unchanged)
// ================================================================================
__global__ void __launch_bounds__(256, 2) proj_kernel(
    const float* __restrict__ q, const float* __restrict__ k, const float* __restrict__ v,
    const float* __restrict__ Wt, const float* __restrict__ Wp, const float* __restrict__ Wg)
{
    extern __shared__ uint32_t dsm[];
    uint32_t* Asm = dsm;              // W tile  [d=128][c=128]
    uint32_t* Bsm = dsm + TILE128;    // in tile [c=128][n=128]

    int which = blockIdx.x;
    int n0    = blockIdx.y * 128;
    int b     = blockIdx.z;
    const float* in = (which == 0) ? q  : (which == 1) ? k  : v;
    const float* Wm = (which == 0) ? Wt : (which == 1) ? Wp : Wg;
    __nv_bfloat16* outp = (which == 0) ? g_qpT : (which == 1) ? g_kpT : g_vpT;

    int tid = threadIdx.x;
    int wid = tid >> 5, lane = tid & 31;
    int wm = wid & 1, wn = wid >> 1;
    int lr = lane >> 2, lk = lane & 3;
    int lg = lane >> 3, li = lane & 7;

    float acc[4][4][4] = {};
    const float* inb = in + ((size_t)b * NC) * NN + n0;
    uint32_t sbB = smem_u32(Bsm);

    uint32_t bAddr[2];
#pragma unroll
    for (int np = 0; np < 2; np++) {
        int brow = ((lg & 1) << 3) + li;
        int bcol = wn * 32 + np * 16 + ((lg >> 1) << 3);
        bAddr[np] = sbB + (uint32_t)brow * 272 + (uint32_t)bcol * 2;
    }

    for (int c0 = 0; c0 < NC; c0 += 128) {
#pragma unroll
        for (int i = 0; i < 16; i++) {
            int idx = tid + i * 256;
            int row = idx >> 5, cq = idx & 31;
            float4 w4 = *(const float4*)(Wm + (size_t)row * NC + c0 + cq * 4);
            Asm[row * KW128 + cq * 2]     = pack_bf2(w4.x, w4.y);
            Asm[row * KW128 + cq * 2 + 1] = pack_bf2(w4.z, w4.w);
        }
#pragma unroll
        for (int i = 0; i < 16; i++) {
            int idx = tid + i * 256;
            int row = idx >> 5, nq = idx & 31;
            float4 v4 = *(const float4*)(inb + (size_t)(c0 + row) * NN + nq * 4);
            Bsm[row * KW128 + nq * 2]     = pack_bf2(v4.x, v4.y);
            Bsm[row * KW128 + nq * 2 + 1] = pack_bf2(v4.z, v4.w);
        }
        __syncthreads();

#pragma unroll
        for (int ks = 0; ks < 8; ks++) {
            int k0w = ks * 8;
            uint32_t a[4][4], bb[2][4];
#pragma unroll
            for (int ma = 0; ma < 4; ma++) {
                int w = (wm * 64 + ma * 16 + lr) * KW128 + k0w + lk;
                a[ma][0] = Asm[w];            a[ma][1] = Asm[w + 8 * KW128];
                a[ma][2] = Asm[w + 4];        a[ma][3] = Asm[w + 8 * KW128 + 4];
            }
#pragma unroll
            for (int np = 0; np < 2; np++)
                ldsm4t(bAddr[np] + (uint32_t)ks * 4352, bb[np]);
#pragma unroll
            for (int ma = 0; ma < 4; ma++)
#pragma unroll
                for (int np = 0; np < 2; np++) {
                    mma16816(acc[ma][2 * np],     a[ma][0], a[ma][1], a[ma][2], a[ma][3], bb[np][0], bb[np][1]);
                    mma16816(acc[ma][2 * np + 1], a[ma][0], a[ma][1], a[ma][2], a[ma][3], bb[np][2], bb[np][3]);
                }
        }
        __syncthreads();
    }

    const float s = (which == 0) ? 0.08838834764831845f : 1.0f;
    uint32_t* ob = (uint32_t*)(outp + (size_t)b * ND * NN);
#pragma unroll
    for (int ma = 0; ma < 4; ma++) {
        int r0 = wm * 64 + ma * 16 + lr;
#pragma unroll
        for (int na = 0; na < 4; na++) {
            int cw = (n0 >> 1) + wn * 16 + na * 4 + lk;
            ob[(size_t)r0 * (NN / 2) + cw]       = pack_bf2(acc[ma][na][0] * s, acc[ma][na][1] * s);
            ob[(size_t)(r0 + 8) * (NN / 2) + cw] = pack_bf2(acc[ma][na][2] * s, acc[ma][na][3] * s);
        }
    }
}

// ================================================================================
// K2 (persistent, R8): qp resident; kp chunks streamed; E store + fused col sums.
// smem: Q [0,34816), K0/K1 [34816, 104448)
// ================================================================================
__global__ void __launch_bounds__(256, 2) s_kernel()
{
    extern __shared__ uint32_t dsm[];
    int tid = threadIdx.x;
    int wid = tid >> 5, lane = tid & 31;
    int wm = wid & 1, wn = wid >> 1;
    int lr = lane >> 2, lk = lane & 3;
    int lg = lane >> 3, li = lane & 7;
    int n0 = blockIdx.x * 128, b = blockIdx.y;
    const __nv_bfloat16* qb = g_qpT + (size_t)b * ND * NN;
    const __nv_bfloat16* kb = g_kpT + (size_t)b * ND * NN;
    uint32_t sb = smem_u32(dsm);

#pragma unroll
    for (int i = 0; i < 8; i++) {
        int idx = tid + i * 256;
        int row = idx >> 4, qx = idx & 15;
        cpa16(sb + (uint32_t)(row * KW128 + qx * 4) * 4,          qb + (size_t)row * NN + n0 + qx * 8);
        cpa16(sb + 34816u + (uint32_t)(row * KW128 + qx * 4) * 4, kb + (size_t)row * NN + qx * 8);
    }
    CP_COMMIT();

    uint32_t aAddr[4], bBase[2];
#pragma unroll
    for (int ma = 0; ma < 4; ma++) {
        int arow = ((lg >> 1) << 3) + li;
        int acol = wm * 64 + ma * 16 + ((lg & 1) << 3);
        aAddr[ma] = sb + (uint32_t)arow * 272 + (uint32_t)acol * 2;
    }
#pragma unroll
    for (int np = 0; np < 2; np++) {
        int brow = ((lg & 1) << 3) + li;
        int bcol = wn * 32 + np * 16 + ((lg >> 1) << 3);
        bBase[np] = sb + (uint32_t)brow * 272 + (uint32_t)bcol * 2;
    }

    uint4* gE4 = (uint4*)g_E;

    for (int mc = 0; mc < 32; mc++) {
        int buf = mc & 1;
        CP_WAIT(0);
        __syncthreads();          // kp(mc) visible; stage reads of chunk mc-1 all done

        if (mc + 1 < 32) {
            uint32_t kB = sb + 34816u + (uint32_t)((mc + 1) & 1) * 34816u;
            const __nv_bfloat16* ksrc = kb + (mc + 1) * 128;
#pragma unroll
            for (int i = 0; i < 8; i++) {
                int idx = tid + i * 256;
                int row = idx >> 4, qx = idx & 15;
                cpa16(kB + (uint32_t)(row * KW128 + qx * 4) * 4, ksrc + (size_t)row * NN + qx * 8);
            }
            CP_COMMIT();
        }

        uint32_t bOff = 34816u + (uint32_t)buf * 34816u;
        float acc[4][4][4] = {};
#pragma unroll
        for (int ks = 0; ks < 8; ks++) {
            uint32_t koff = (uint32_t)ks * 4352;
            uint32_t a[4][4], bb[2][4];
#pragma unroll
            for (int ma = 0; ma < 4; ma++) ldsm4t(aAddr[ma] + koff, a[ma]);
#pragma unroll
            for (int np = 0; np < 2; np++) ldsm4t(bBase[np] + bOff + koff, bb[np]);
#pragma unroll
            for (int ma = 0; ma < 4; ma++)
#pragma unroll
                for (int np = 0; np < 2; np++) {
                    mma16816(acc[ma][2 * np],     a[ma][0], a[ma][1], a[ma][2], a[ma][3], bb[np][0], bb[np][1]);
                    mma16816(acc[ma][2 * np + 1], a[ma][0], a[ma][1], a[ma][2], a[ma][3], bb[np][2], bb[np][3]);
                }
        }
        __syncthreads();   // kp[buf] free -> reuse as E stage

        uint32_t* stage = dsm + 8704 + buf * 8704;
        float s0[4] = {}, s1[4] = {};
#pragma unroll
        for (int ma = 0; ma < 4; ma++) {
            int r0 = wm * 64 + ma * 16 + lr;
#pragma unroll
            for (int na = 0; na < 4; na++) {
                int cw = wn * 16 + na * 4 + lk;
                float e00 = fexp(acc[ma][na][0]), e01 = fexp(acc[ma][na][1]);
                float e10 = fexp(acc[ma][na][2]), e11 = fexp(acc[ma][na][3]);
                stage[r0 * 68 + cw]       = pack_bf2(e00, e01);
                stage[(r0 + 8) * 68 + cw] = pack_bf2(e10, e11);
                s0[na] += e00 + e10;
                s1[na] += e01 + e11;
            }
        }
#pragma unroll
        for (int na = 0; na < 4; na++) {
#pragma unroll
            for (int off = 4; off < 32; off <<= 1) {
                s0[na] += __shfl_xor_sync(0xffffffffu, s0[na], off);
                s1[na] += __shfl_xor_sync(0xffffffffu, s1[na], off);
            }
        }
        if (lane < 4) {
#pragma unroll
            for (int na = 0; na < 4; na++) {
                int col = mc * 128 + wn * 32 + na * 8 + lane * 2;
                atomicAdd(&g_sum[b * NN + col], s0[na]);
                atomicAdd(&g_sum[b * NN + col + 1], s1[na]);
            }
        }
        __syncthreads();   // stage complete

        size_t ebase = ((size_t)(b * NN + n0)) << 9;
        int mq = mc * 16;
#pragma unroll
        for (int i = 0; i < 8; i++) {
            int idx = tid + i * 256;
            int row = idx >> 4, qx = idx & 15;
            gE4[ebase + ((size_t)row << 9) + mq + qx] = *(uint4*)&stage[row * 68 + qx * 4];
        }
    }
}

// ================================================================================
// K3: vpT[b,d,m] *= 1/sum[b,m]
// ================================================================================
__global__ void __launch_bounds__(256) vscale_kernel()
{
    int idx = blockIdx.x * 256 + threadIdx.x;
    int e4 = idx << 2;
    int b = e4 >> 19;
    int m = e4 & (NN - 1);
    uint2 w = *(uint2*)&g_vpT[e4];
    float4 s4 = *(const float4*)&g_sum[b * NN + m];
    __nv_bfloat162 p0 = *(__nv_bfloat162*)&w.x;
    __nv_bfloat162 p1 = *(__nv_bfloat162*)&w.y;
    float2 f0 = __bfloat1622float2(p0);
    float2 f1 = __bfloat1622float2(p1);
    uint2 o;
    o.x = pack_bf2(f0.x / s4.x, f0.y / s4.y);
    o.y = pack_bf2(f1.x / s4.z, f1.y / s4.w);
    *(uint2*)&g_vpT[e4] = o;
}

// ================================================================================
// K4: avh[n][d] = sum_m E[n][m] * vpT[d][m]  -- 64-row tiles, 3 CTAs/SM.
// grid (NN/64, NB), 256 threads. 2-stage cp.async, 1 barrier/iter.
// stage: A = E[64 n-rows][64 m] at +0 (144 B rows), B = vp[128 d-rows][64 m] at +9216.
// ================================================================================
__global__ void __launch_bounds__(256, 3) pv_kernel()
{
    extern __shared__ uint32_t dsm[];
    int tid = threadIdx.x;
    int wid = tid >> 5, lane = tid & 31;
    int lr = lane >> 2, lk = lane & 3;
    int lg = lane >> 3, li = lane & 7;
    int wm = wid & 1;            // 2 warp-rows over n (32 each)
    int wn = wid >> 1;           // 4 warp-cols over d (32 each)
    int n0 = blockIdx.x * 64, b = blockIdx.y;
    const __nv_bfloat16* Eb = g_E   + (size_t)b * NN * NN;
    const __nv_bfloat16* vt = g_vpT + (size_t)b * ND * NN;
    uint32_t sb = smem_u32(dsm);

    float acc[2][4][4] = {};

    // ldmatrix lane base offsets (bytes, within a stage)
    uint32_t aBase[2], bBase[2];
#pragma unroll
    for (int ma = 0; ma < 2; ma++)
        aBase[ma] = (uint32_t)(wm * 32 + ma * 16 + ((lg & 1) << 3) + li) * 144 + ((lg >> 1) << 4);
#pragma unroll
    for (int np = 0; np < 2; np++)
        bBase[np] = 9216u + (uint32_t)(wn * 32 + np * 16 + ((lg >> 1) << 3) + li) * 144 + ((lg & 1) << 4);

    auto issue = [&](int stg, int m0) {
        uint32_t aB = sb + (uint32_t)stg * PV_STAGE;
        uint32_t bB = aB + 9216u;
#pragma unroll
        for (int i = 0; i < 2; i++) {          // A: 64 rows x 8 x 16B
            int idx = tid + i * 256;
            int row = idx >> 3, qx = idx & 7;
            cpa16(aB + (uint32_t)(row * 144 + qx * 16), Eb + (size_t)(n0 + row) * NN + m0 + qx * 8);
        }
#pragma unroll
        for (int i = 0; i < 4; i++) {          // B: 128 rows x 8 x 16B
            int idx = tid + i * 256;
            int row = idx >> 3, qx = idx & 7;
            cpa16(bB + (uint32_t)(row * 144 + qx * 16), vt + (size_t)row * NN + m0 + qx * 8);
        }
        CP_COMMIT();
    };

    issue(0, 0);
    for (int it = 0; it < 64; it++) {
        int buf = it & 1;
        CP_WAIT(0);
        __syncthreads();          // stage(it) visible; reads of stage(it-1) all done
        if (it + 1 < 64) issue(buf ^ 1, (it + 1) * 64);

        uint32_t sOff = sb + (uint32_t)buf * PV_STAGE;
#pragma unroll
        for (int ks = 0; ks < 4; ks++) {
            uint32_t koff = (uint32_t)ks * 32;
            uint32_t a[2][4], bb[2][4];
#pragma unroll
            for (int ma = 0; ma < 2; ma++) ldsm4(sOff + aBase[ma] + koff, a[ma]);
#pragma unroll
            for (int np = 0; np < 2; np++) ldsm4(sOff + bBase[np] + koff, bb[np]);
#pragma unroll
            for (int ma = 0; ma < 2; ma++)
#pragma unroll
                for (int np = 0; np < 2; np++) {
                    mma16816(acc[ma][2 * np],     a[ma][0], a[ma][1], a[ma][2], a[ma][3], bb[np][0], bb[np][1]);
                    mma16816(acc[ma][2 * np + 1], a[ma][0], a[ma][1], a[ma][2], a[ma][3], bb[np][2], bb[np][3]);
                }
        }
    }

    // epilogue: bf16 [n][d] direct stores
    uint32_t* ob = (uint32_t*)(g_avh + ((size_t)b * NN + n0) * ND);
#pragma unroll
    for (int ma = 0; ma < 2; ma++) {
        int r0 = wm * 32 + ma * 16 + lr;
#pragma unroll
        for (int na = 0; na < 4; na++) {
            int cw = wn * 16 + na * 4 + lk;
            ob[(size_t)r0 * (ND / 2) + cw]       = pack_bf2(acc[ma][na][0], acc[ma][na][1]);
            ob[(size_t)(r0 + 8) * (ND / 2) + cw] = pack_bf2(acc[ma][na][2], acc[ma][na][3]);
        }
    }
}

// ================================================================================
// K5: y[c][n] = v[c][n] + sum_d Wo[c][d] * avh[n][d]   (R8, unchanged)
// ================================================================================
__global__ void __launch_bounds__(256, 2) final_kernel(const float* __restrict__ vin,
                                                       const float* __restrict__ Wo,
                                                       float* __restrict__ y)
{
    extern __shared__ uint32_t dsm[];
    uint32_t* Asm = dsm;              // Wo tile [c=128][d=128]
    uint32_t* Bsm = dsm + TILE128;    // avh tile [n=128][d=128]

    int tid = threadIdx.x;
    int wid = tid >> 5, lane = tid & 31;
    int wm = wid & 1, wn = wid >> 1;
    int lr = lane >> 2, lk = lane & 3;
    int n0 = blockIdx.x * 128, c0 = blockIdx.y * 128, b = blockIdx.z;
    const __nv_bfloat16* ab = g_avh + ((size_t)b * NN + n0) * ND;

#pragma unroll
    for (int i = 0; i < 16; i++) {
        int idx = tid + i * 256;
        int row = idx >> 5, dq = idx & 31;
        float4 w4 = *(const float4*)(Wo + (size_t)(c0 + row) * ND + dq * 4);
        Asm[row * KW128 + dq * 2]     = pack_bf2(w4.x, w4.y);
        Asm[row * KW128 + dq * 2 + 1] = pack_bf2(w4.z, w4.w);
    }
#pragma unroll
    for (int i = 0; i < 8; i++) {
        int idx = tid + i * 256;
        int row = idx >> 4, qx = idx & 15;
        *(uint4*)&Bsm[row * KW128 + qx * 4] = *(const uint4*)(ab + (size_t)row * ND + qx * 8);
    }
    __syncthreads();

    float acc[4][4][4] = {};
#pragma unroll
    for (int ks = 0; ks < 8; ks++) {
        int k0w = ks * 8;
        uint32_t a[4][4], bb[4][2];
#pragma unroll
        for (int ma = 0; ma < 4; ma++) {
            int w = (wm * 64 + ma * 16 + lr) * KW128 + k0w + lk;
            a[ma][0] = Asm[w];            a[ma][1] = Asm[w + 8 * KW128];
            a[ma][2] = Asm[w + 4];        a[ma][3] = Asm[w + 8 * KW128 + 4];
        }
#pragma unroll
        for (int na = 0; na < 4; na++) {
            int w = (wn * 32 + na * 8 + lr) * KW128 + k0w + lk;
            bb[na][0] = Bsm[w];           bb[na][1] = Bsm[w + 4];
        }
#pragma unroll
        for (int ma = 0; ma < 4; ma++)
#pragma unroll
            for (int na = 0; na < 4; na++)
                mma16816(acc[ma][na], a[ma][0], a[ma][1], a[ma][2], a[ma][3],
                         bb[na][0], bb[na][1]);
    }

    const float* vb = vin + ((size_t)b * NC + c0) * NN + n0;
    float*       yb = y   + ((size_t)b * NC + c0) * NN + n0;
#pragma unroll
    for (int ma = 0; ma < 4; ma++) {
        int r0 = wm * 64 + ma * 16 + lr;
#pragma unroll
        for (int na = 0; na < 4; na++) {
            int c = wn * 32 + na * 8 + lk * 2;
            float2 v0 = *(const float2*)(vb + (size_t)r0 * NN + c);
            float2 v1 = *(const float2*)(vb + (size_t)(r0 + 8) * NN + c);
            *(float2*)(yb + (size_t)r0 * NN + c)       = make_float2(acc[ma][na][0] + v0.x, acc[ma][na][1] + v0.y);
            *(float2*)(yb + (size_t)(r0 + 8) * NN + c) = make_float2(acc[ma][na][2] + v1.x, acc[ma][na][3] + v1.y);
        }
    }
}

// ================================================================================
extern "C" void kernel_launch(void* const* d_in, const int* in_sizes, int n_in,
                              void* d_out, int out_size)
{
    const float* q  = (const float*)d_in[0];
    const float* k  = (const float*)d_in[1];
    const float* v  = (const float*)d_in[2];
    const float* Wt = (const float*)d_in[3];
    const float* Wp = (const float*)d_in[4];
    const float* Wg = (const float*)d_in[5];
    const float* Wo = (const float*)d_in[6];
    float* y = (float*)d_out;

    cudaFuncSetAttribute(proj_kernel,  cudaFuncAttributeMaxDynamicSharedMemorySize, 2 * TILE128 * 4);
    cudaFuncSetAttribute(s_kernel,     cudaFuncAttributeMaxDynamicSharedMemorySize, 3 * TILE128 * 4);
    cudaFuncSetAttribute(pv_kernel,    cudaFuncAttributeMaxDynamicSharedMemorySize, PV_SMEM);
    cudaFuncSetAttribute(final_kernel, cudaFuncAttributeMaxDynamicSharedMemorySize, 2 * TILE128 * 4);

    void* sumAddr = nullptr;
    cudaGetSymbolAddress(&sumAddr, g_sum);
    cudaMemsetAsync(sumAddr, 0, NB * NN * sizeof(float));

    proj_kernel  <<<dim3(3, NN / 128, NB), 256, 2 * TILE128 * 4>>>(q, k, v, Wt, Wp, Wg);
    s_kernel     <<<dim3(NN / 128, NB), 256, 3 * TILE128 * 4>>>();
    vscale_kernel<<<dim3((NB * ND * NN / 4) / 256), 256>>>();
    pv_kernel    <<<dim3(NN / 64, NB), 256, PV_SMEM>>>();
    final_kernel <<<dim3(NN / 128, NC / 128, NB), 256, 2 * TILE128 * 4>>>(v, Wo, y);
}

// round 16
// speedup vs baseline: 1.5765x; 1.5765x over previous
#include <cuda_runtime.h>
#include <cuda_bf16.h>
#include <cstdint>

#define NB 8
#define NC 256
#define ND 128
#define NN 4096   // 64*64

// ---------------- scratch (static device globals; no allocation) ----------------
__device__ __nv_bfloat16 g_qpT[(size_t)NB * ND * NN];     // 8 MB [b][d][n], pre-scaled 1/sqrt(D)
__device__ __nv_bfloat16 g_kpT[(size_t)NB * ND * NN];     // 8 MB [b][d][m]
__device__ __nv_bfloat16 g_vpT[(size_t)NB * ND * NN];     // 8 MB [b][d][m]
__device__ __nv_bfloat16 g_avh[(size_t)NB * NN * ND];     // 8 MB attention out [b][n][d]
__device__ uint4         g_E8[(size_t)NB * NN * NN / 16]; // 134 MB e4m3 E [b][n][m]
__device__ uint4         g_vp8[(size_t)NB * ND * NN / 16];// 4 MB  e4m3 vp*4096/sum [b][d][m]
__device__ float         g_sum[NB * NN];                  // column sums of E over n

// ---------------- fast exp (FFMA-only) -------------------------------------------
__device__ __forceinline__ float fexp(float x) {
    x = fmaxf(x, -30.0f);
    float t  = fmaf(x, 1.4426950408889634f, 12582912.0f);
    int   i  = __float_as_int(t);
    float fi = t - 12582912.0f;
    float f  = fmaf(x, 1.4426950408889634f, -fi);
    float p  = 9.6181291e-3f;
    p = fmaf(p, f, 5.5504109e-2f);
    p = fmaf(p, f, 2.4022651e-1f);
    p = fmaf(p, f, 6.9314718e-1f);
    p = fmaf(p, f, 1.0f);
    return __int_as_float(__float_as_int(p) + (i << 23));
}
__device__ __forceinline__ uint32_t pack_bf2(float a, float b) {
    __nv_bfloat162 h = __floats2bfloat162_rn(a, b);
    return *reinterpret_cast<uint32_t*>(&h);
}
__device__ __forceinline__ uint16_t cvt_e4m3x2(float hi, float lo) {
    uint16_t r;
    asm("cvt.rn.satfinite.e4m3x2.f32 %0, %1, %2;" : "=h"(r) : "f"(hi), "f"(lo));
    return r;
}

// ---------------- HMMA + ldmatrix + cp.async helpers -----------------------------
__device__ __forceinline__ void mma16816(float* d,
                                         uint32_t a0, uint32_t a1, uint32_t a2, uint32_t a3,
                                         uint32_t b0, uint32_t b1) {
    asm volatile(
        "mma.sync.aligned.m16n8k16.row.col.f32.bf16.bf16.f32 "
        "{%0,%1,%2,%3}, {%4,%5,%6,%7}, {%8,%9}, {%0,%1,%2,%3};"
        : "+f"(d[0]), "+f"(d[1]), "+f"(d[2]), "+f"(d[3])
        : "r"(a0), "r"(a1), "r"(a2), "r"(a3), "r"(b0), "r"(b1));
}
__device__ __forceinline__ void mma16832f8(float* d,
                                           uint32_t a0, uint32_t a1, uint32_t a2, uint32_t a3,
                                           uint32_t b0, uint32_t b1) {
    asm volatile(
        "mma.sync.aligned.m16n8k32.row.col.f32.e4m3.e4m3.f32 "
        "{%0,%1,%2,%3}, {%4,%5,%6,%7}, {%8,%9}, {%0,%1,%2,%3};"
        : "+f"(d[0]), "+f"(d[1]), "+f"(d[2]), "+f"(d[3])
        : "r"(a0), "r"(a1), "r"(a2), "r"(a3), "r"(b0), "r"(b1));
}
__device__ __forceinline__ void ldsm4t(uint32_t addr, uint32_t* r) {
    asm volatile("ldmatrix.sync.aligned.m8n8.x4.trans.shared.b16 {%0,%1,%2,%3}, [%4];"
                 : "=r"(r[0]), "=r"(r[1]), "=r"(r[2]), "=r"(r[3]) : "r"(addr));
}
__device__ __forceinline__ void ldsm4(uint32_t addr, uint32_t* r) {
    asm volatile("ldmatrix.sync.aligned.m8n8.x4.shared.b16 {%0,%1,%2,%3}, [%4];"
                 : "=r"(r[0]), "=r"(r[1]), "=r"(r[2]), "=r"(r[3]) : "r"(addr));
}
__device__ __forceinline__ void cpa16(uint32_t dst, const void* src) {
    asm volatile("cp.async.cg.shared.global [%0], [%1], 16;" :: "r"(dst), "l"(src) : "memory");
}
#define CP_COMMIT() asm volatile("cp.async.commit_group;" ::: "memory")
#define CP_WAIT(n)  asm volatile("cp.async.wait_group %0;" :: "n"(n) : "memory")
__device__ __forceinline__ uint32_t smem_u32(const void* p) {
    return (uint32_t)__cvta_generic_to_shared(p);
}

// smem row strides: 128 bf16 + 8 pad = 68 words (272 B)
#define KW128 68
#define TILE128 (128 * KW128)     // 34816 B
// pv fp8 rows: 64 B data + 16 pad = 80 B (20 words ≡ 4 mod 32 -> conflict-free)
#define F8ROW 80
// s_kernel fp8 E stage rows: 128 B data + 16 pad = 144 B (36 words ≡ 4 mod 32)
#define SROW 144
#define PV_STAGE 20480            // A (128x80) + B (128x80)
#define PV_SMEM  (3 * PV_STAGE)   // 61440 B

// ================================================================================
// K1: projections -> TRANSPOSED outputs [d][n].  (R8, unchanged)
// ================================================================================
__global__ void __launch_bounds__(256, 2) proj_kernel(
    const float* __restrict__ q, const float* __restrict__ k, const float* __restrict__ v,
    const float* __restrict__ Wt, const float* __restrict__ Wp, const float* __restrict__ Wg)
{
    extern __shared__ uint32_t dsm[];
    uint32_t* Asm = dsm;              // W tile  [d=128][c=128]
    uint32_t* Bsm = dsm + TILE128;    // in tile [c=128][n=128]

    int which = blockIdx.x;
    int n0    = blockIdx.y * 128;
    int b     = blockIdx.z;
    const float* in = (which == 0) ? q  : (which == 1) ? k  : v;
    const float* Wm = (which == 0) ? Wt : (which == 1) ? Wp : Wg;
    __nv_bfloat16* outp = (which == 0) ? g_qpT : (which == 1) ? g_kpT : g_vpT;

    int tid = threadIdx.x;
    int wid = tid >> 5, lane = tid & 31;
    int wm = wid & 1, wn = wid >> 1;
    int lr = lane >> 2, lk = lane & 3;
    int lg = lane >> 3, li = lane & 7;

    float acc[4][4][4] = {};
    const float* inb = in + ((size_t)b * NC) * NN + n0;
    uint32_t sbB = smem_u32(Bsm);

    uint32_t bAddr[2];
#pragma unroll
    for (int np = 0; np < 2; np++) {
        int brow = ((lg & 1) << 3) + li;
        int bcol = wn * 32 + np * 16 + ((lg >> 1) << 3);
        bAddr[np] = sbB + (uint32_t)brow * 272 + (uint32_t)bcol * 2;
    }

    for (int c0 = 0; c0 < NC; c0 += 128) {
#pragma unroll
        for (int i = 0; i < 16; i++) {
            int idx = tid + i * 256;
            int row = idx >> 5, cq = idx & 31;
            float4 w4 = *(const float4*)(Wm + (size_t)row * NC + c0 + cq * 4);
            Asm[row * KW128 + cq * 2]     = pack_bf2(w4.x, w4.y);
            Asm[row * KW128 + cq * 2 + 1] = pack_bf2(w4.z, w4.w);
        }
#pragma unroll
        for (int i = 0; i < 16; i++) {
            int idx = tid + i * 256;
            int row = idx >> 5, nq = idx & 31;
            float4 v4 = *(const float4*)(inb + (size_t)(c0 + row) * NN + nq * 4);
            Bsm[row * KW128 + nq * 2]     = pack_bf2(v4.x, v4.y);
            Bsm[row * KW128 + nq * 2 + 1] = pack_bf2(v4.z, v4.w);
        }
        __syncthreads();

#pragma unroll
        for (int ks = 0; ks < 8; ks++) {
            int k0w = ks * 8;
            uint32_t a[4][4], bb[2][4];
#pragma unroll
            for (int ma = 0; ma < 4; ma++) {
                int w = (wm * 64 + ma * 16 + lr) * KW128 + k0w + lk;
                a[ma][0] = Asm[w];            a[ma][1] = Asm[w + 8 * KW128];
                a[ma][2] = Asm[w + 4];        a[ma][3] = Asm[w + 8 * KW128 + 4];
            }
#pragma unroll
            for (int np = 0; np < 2; np++)
                ldsm4t(bAddr[np] + (uint32_t)ks * 4352, bb[np]);
#pragma unroll
            for (int ma = 0; ma < 4; ma++)
#pragma unroll
                for (int np = 0; np < 2; np++) {
                    mma16816(acc[ma][2 * np],     a[ma][0], a[ma][1], a[ma][2], a[ma][3], bb[np][0], bb[np][1]);
                    mma16816(acc[ma][2 * np + 1], a[ma][0], a[ma][1], a[ma][2], a[ma][3], bb[np][2], bb[np][3]);
                }
        }
        __syncthreads();
    }

    const float s = (which == 0) ? 0.08838834764831845f : 1.0f;
    uint32_t* ob = (uint32_t*)(outp + (size_t)b * ND * NN);
#pragma unroll
    for (int ma = 0; ma < 4; ma++) {
        int r0 = wm * 64 + ma * 16 + lr;
#pragma unroll
        for (int na = 0; na < 4; na++) {
            int cw = (n0 >> 1) + wn * 16 + na * 4 + lk;
            ob[(size_t)r0 * (NN / 2) + cw]       = pack_bf2(acc[ma][na][0] * s, acc[ma][na][1] * s);
            ob[(size_t)(r0 + 8) * (NN / 2) + cw] = pack_bf2(acc[ma][na][2] * s, acc[ma][na][3] * s);
        }
    }
}

// ================================================================================
// K2 (persistent): qp resident; kp chunks streamed; E stored as e4m3; col sums fused.
// smem: Q [0,34816), K0/K1 [34816, 104448); fp8 stage (128 rows x SROW=144 B)
// reuses the retiring kp buffer (18432 B < 34816 B).
// ================================================================================
__global__ void __launch_bounds__(256, 2) s_kernel()
{
    extern __shared__ uint32_t dsm[];
    int tid = threadIdx.x;
    int wid = tid >> 5, lane = tid & 31;
    int wm = wid & 1, wn = wid >> 1;
    int lr = lane >> 2, lk = lane & 3;
    int lg = lane >> 3, li = lane & 7;
    int n0 = blockIdx.x * 128, b = blockIdx.y;
    const __nv_bfloat16* qb = g_qpT + (size_t)b * ND * NN;
    const __nv_bfloat16* kb = g_kpT + (size_t)b * ND * NN;
    uint32_t sb = smem_u32(dsm);

#pragma unroll
    for (int i = 0; i < 8; i++) {
        int idx = tid + i * 256;
        int row = idx >> 4, qx = idx & 15;
        cpa16(sb + (uint32_t)(row * KW128 + qx * 4) * 4,          qb + (size_t)row * NN + n0 + qx * 8);
        cpa16(sb + 34816u + (uint32_t)(row * KW128 + qx * 4) * 4, kb + (size_t)row * NN + qx * 8);
    }
    CP_COMMIT();

    uint32_t aAddr[4], bBase[2];
#pragma unroll
    for (int ma = 0; ma < 4; ma++) {
        int arow = ((lg >> 1) << 3) + li;
        int acol = wm * 64 + ma * 16 + ((lg & 1) << 3);
        aAddr[ma] = sb + (uint32_t)arow * 272 + (uint32_t)acol * 2;
    }
#pragma unroll
    for (int np = 0; np < 2; np++) {
        int brow = ((lg & 1) << 3) + li;
        int bcol = wn * 32 + np * 16 + ((lg >> 1) << 3);
        bBase[np] = sb + (uint32_t)brow * 272 + (uint32_t)bcol * 2;
    }

    uint4* gE4 = (uint4*)g_E8;                 // E8 row = 4096 B = 256 uint4

    for (int mc = 0; mc < 32; mc++) {
        int buf = mc & 1;
        CP_WAIT(0);
        __syncthreads();          // kp(mc) visible; stage reads of chunk mc-1 all done

        if (mc + 1 < 32) {
            uint32_t kB = sb + 34816u + (uint32_t)((mc + 1) & 1) * 34816u;
            const __nv_bfloat16* ksrc = kb + (mc + 1) * 128;
#pragma unroll
            for (int i = 0; i < 8; i++) {
                int idx = tid + i * 256;
                int row = idx >> 4, qx = idx & 15;
                cpa16(kB + (uint32_t)(row * KW128 + qx * 4) * 4, ksrc + (size_t)row * NN + qx * 8);
            }
            CP_COMMIT();
        }

        uint32_t bOff = 34816u + (uint32_t)buf * 34816u;
        float acc[4][4][4] = {};
#pragma unroll
        for (int ks = 0; ks < 8; ks++) {
            uint32_t koff = (uint32_t)ks * 4352;
            uint32_t a[4][4], bb[2][4];
#pragma unroll
            for (int ma = 0; ma < 4; ma++) ldsm4t(aAddr[ma] + koff, a[ma]);
#pragma unroll
            for (int np = 0; np < 2; np++) ldsm4t(bBase[np] + bOff + koff, bb[np]);
#pragma unroll
            for (int ma = 0; ma < 4; ma++)
#pragma unroll
                for (int np = 0; np < 2; np++) {
                    mma16816(acc[ma][2 * np],     a[ma][0], a[ma][1], a[ma][2], a[ma][3], bb[np][0], bb[np][1]);
                    mma16816(acc[ma][2 * np + 1], a[ma][0], a[ma][1], a[ma][2], a[ma][3], bb[np][2], bb[np][3]);
                }
        }
        __syncthreads();   // kp[buf] free -> reuse as fp8 E stage (128 rows x 144 B)

        uint8_t* stageB = (uint8_t*)(dsm + 8704 + buf * 8704);
        uint16_t* stage16 = (uint16_t*)stageB;
        float s0[4] = {}, s1[4] = {};
#pragma unroll
        for (int ma = 0; ma < 4; ma++) {
            int r0 = wm * 64 + ma * 16 + lr;
#pragma unroll
            for (int na = 0; na < 4; na++) {
                int cw = wn * 16 + na * 4 + lk;     // uint16 col (2 m per entry), 0..63
                float e00 = fexp(acc[ma][na][0]), e01 = fexp(acc[ma][na][1]);
                float e10 = fexp(acc[ma][na][2]), e11 = fexp(acc[ma][na][3]);
                stage16[r0 * (SROW / 2) + cw]       = cvt_e4m3x2(e01, e00);
                stage16[(r0 + 8) * (SROW / 2) + cw] = cvt_e4m3x2(e11, e10);
                s0[na] += e00 + e10;
                s1[na] += e01 + e11;
            }
        }
#pragma unroll
        for (int na = 0; na < 4; na++) {
#pragma unroll
            for (int off = 4; off < 32; off <<= 1) {
                s0[na] += __shfl_xor_sync(0xffffffffu, s0[na], off);
                s1[na] += __shfl_xor_sync(0xffffffffu, s1[na], off);
            }
        }
        if (lane < 4) {
#pragma unroll
            for (int na = 0; na < 4; na++) {
                int col = mc * 128 + wn * 32 + na * 8 + lane * 2;
                atomicAdd(&g_sum[b * NN + col], s0[na]);
                atomicAdd(&g_sum[b * NN + col + 1], s1[na]);
            }
        }
        __syncthreads();   // stage complete

        // store 128 rows x 128 B to E8 (chunk column block: 8 uint4 per row)
        size_t base8 = ((size_t)(b * NN + n0)) << 8;   // uint4 per row = 256
#pragma unroll
        for (int i = 0; i < 4; i++) {
            int idx = tid + i * 256;
            int row = idx >> 3, qx = idx & 7;
            gE4[base8 + ((size_t)row << 8) + mc * 8 + qx] =
                *(uint4*)(stageB + row * SROW + qx * 16);
        }
    }
}

// ================================================================================
// K3: vp8[b,d,m] = e4m3( vpT * 4096 / sum[m] )   (8 bytes per thread)
// ================================================================================
__global__ void __launch_bounds__(256) vscale_kernel()
{
    int idx = blockIdx.x * 256 + threadIdx.x;          // 524288 threads
    size_t e8 = (size_t)idx << 3;
    int b = (int)(e8 >> 19);
    int m = (int)(e8 & (NN - 1));
    uint4 w = *(uint4*)&g_vpT[e8];                     // 8 bf16
    const float* sp = &g_sum[b * NN + m];
    float f[8];
    float2 t;
    t = __bfloat1622float2(*(__nv_bfloat162*)&w.x); f[0] = t.x; f[1] = t.y;
    t = __bfloat1622float2(*(__nv_bfloat162*)&w.y); f[2] = t.x; f[3] = t.y;
    t = __bfloat1622float2(*(__nv_bfloat162*)&w.z); f[4] = t.x; f[5] = t.y;
    t = __bfloat1622float2(*(__nv_bfloat162*)&w.w); f[6] = t.x; f[7] = t.y;
#pragma unroll
    for (int i = 0; i < 8; i++) f[i] = f[i] * 4096.0f / sp[i];
    uint16_t p01 = cvt_e4m3x2(f[1], f[0]);
    uint16_t p23 = cvt_e4m3x2(f[3], f[2]);
    uint16_t p45 = cvt_e4m3x2(f[5], f[4]);
    uint16_t p67 = cvt_e4m3x2(f[7], f[6]);
    uint2 o;
    o.x = (uint32_t)p01 | ((uint32_t)p23 << 16);
    o.y = (uint32_t)p45 | ((uint32_t)p67 << 16);
    *(uint2*)((uint8_t*)g_vp8 + e8) = o;
}

// ================================================================================
// K4: avh[n][d] = sum_m E8[n][m] * vp8[d][m]   (fp8 mma k32, K=4096,
// 3-stage cp.async, single barrier per iteration; R8 pipeline shape)
// stage: A = E8[128 n-rows][64 m] rows 80 B; B = vp8[128 d-rows][64 m] at +10240.
// ================================================================================
__global__ void __launch_bounds__(256, 2) pv_kernel()
{
    extern __shared__ uint32_t dsm[];
    int tid = threadIdx.x;
    int wid = tid >> 5, lane = tid & 31;
    int wm = wid & 1, wn = wid >> 1;
    int lr = lane >> 2, lk = lane & 3;
    int lg = lane >> 3, li = lane & 7;
    int n0 = blockIdx.x * 128, b = blockIdx.y;
    const uint8_t* Eb = (const uint8_t*)g_E8  + (size_t)b * NN * NN;
    const uint8_t* vt = (const uint8_t*)g_vp8 + (size_t)b * ND * NN;
    uint32_t sb = smem_u32(dsm);

    float acc[4][4][4] = {};

    // ldmatrix lane base offsets (bytes, within a stage) — fp8 rows 80 B
    uint32_t aBase[4], bBase[2];
#pragma unroll
    for (int ma = 0; ma < 4; ma++)
        aBase[ma] = (uint32_t)(wm * 64 + ma * 16 + ((lg & 1) << 3) + li) * F8ROW + ((lg >> 1) << 4);
#pragma unroll
    for (int np = 0; np < 2; np++)
        bBase[np] = 10240u + (uint32_t)(wn * 32 + np * 16 + ((lg >> 1) << 3) + li) * F8ROW + ((lg & 1) << 4);

    auto issue = [&](int stg, int m0) {
        uint32_t aB = sb + (uint32_t)stg * PV_STAGE;
        uint32_t bB = aB + 10240u;
#pragma unroll
        for (int i = 0; i < 2; i++) {
            int idx = tid + i * 256;
            int row = idx >> 2, qx = idx & 3;
            cpa16(aB + (uint32_t)(row * F8ROW + qx * 16), Eb + (size_t)(n0 + row) * NN + m0 + qx * 16);
            cpa16(bB + (uint32_t)(row * F8ROW + qx * 16), vt + (size_t)row * NN + m0 + qx * 16);
        }
        CP_COMMIT();
    };

    issue(0, 0);
    issue(1, 64);
    int stg = 0;
    for (int it = 0; it < 64; it++) {
        if (it < 63) { CP_WAIT(1); } else { CP_WAIT(0); }
        __syncthreads();                 // stage(it) visible; reads of stage(it-1) done
        if (it + 2 < 64) issue((it + 2) % 3, (it + 2) * 64);

        uint32_t sOff = sb + (uint32_t)stg * PV_STAGE;
#pragma unroll
        for (int ks = 0; ks < 2; ks++) {               // k32 per mma, 64 m per chunk
            uint32_t koff = (uint32_t)ks * 32;
            uint32_t a[4][4], bb[2][4];
#pragma unroll
            for (int ma = 0; ma < 4; ma++) ldsm4(sOff + aBase[ma] + koff, a[ma]);
#pragma unroll
            for (int np = 0; np < 2; np++) ldsm4(sOff + bBase[np] + koff, bb[np]);
#pragma unroll
            for (int ma = 0; ma < 4; ma++)
#pragma unroll
                for (int np = 0; np < 2; np++) {
                    mma16832f8(acc[ma][2 * np],     a[ma][0], a[ma][1], a[ma][2], a[ma][3], bb[np][0], bb[np][1]);
                    mma16832f8(acc[ma][2 * np + 1], a[ma][0], a[ma][1], a[ma][2], a[ma][3], bb[np][2], bb[np][3]);
                }
        }
        stg = (stg + 1) % 3;
    }

    // epilogue: undo the 4096 pre-scale, bf16 [n][d] stores
    const float us = 0.000244140625f;   // 2^-12
    uint32_t* ob = (uint32_t*)(g_avh + ((size_t)b * NN + n0) * ND);
#pragma unroll
    for (int ma = 0; ma < 4; ma++) {
        int r0 = wm * 64 + ma * 16 + lr;
#pragma unroll
        for (int na = 0; na < 4; na++) {
            int cw = wn * 16 + na * 4 + lk;
            ob[(size_t)r0 * (ND / 2) + cw]       = pack_bf2(acc[ma][na][0] * us, acc[ma][na][1] * us);
            ob[(size_t)(r0 + 8) * (ND / 2) + cw] = pack_bf2(acc[ma][na][2] * us, acc[ma][na][3] * us);
        }
    }
}

// ================================================================================
// K5: y[c][n] = v[c][n] + sum_d Wo[c][d] * avh[n][d]   (R8, unchanged)
// ================================================================================
__global__ void __launch_bounds__(256, 2) final_kernel(const float* __restrict__ vin,
                                                       const float* __restrict__ Wo,
                                                       float* __restrict__ y)
{
    extern __shared__ uint32_t dsm[];
    uint32_t* Asm = dsm;              // Wo tile [c=128][d=128]
    uint32_t* Bsm = dsm + TILE128;    // avh tile [n=128][d=128]

    int tid = threadIdx.x;
    int wid = tid >> 5, lane = tid & 31;
    int wm = wid & 1, wn = wid >> 1;
    int lr = lane >> 2, lk = lane & 3;
    int n0 = blockIdx.x * 128, c0 = blockIdx.y * 128, b = blockIdx.z;
    const __nv_bfloat16* ab = g_avh + ((size_t)b * NN + n0) * ND;

#pragma unroll
    for (int i = 0; i < 16; i++) {
        int idx = tid + i * 256;
        int row = idx >> 5, dq = idx & 31;
        float4 w4 = *(const float4*)(Wo + (size_t)(c0 + row) * ND + dq * 4);
        Asm[row * KW128 + dq * 2]     = pack_bf2(w4.x, w4.y);
        Asm[row * KW128 + dq * 2 + 1] = pack_bf2(w4.z, w4.w);
    }
#pragma unroll
    for (int i = 0; i < 8; i++) {
        int idx = tid + i * 256;
        int row = idx >> 4, qx = idx & 15;
        *(uint4*)&Bsm[row * KW128 + qx * 4] = *(const uint4*)(ab + (size_t)row * ND + qx * 8);
    }
    __syncthreads();

    float acc[4][4][4] = {};
#pragma unroll
    for (int ks = 0; ks < 8; ks++) {
        int k0w = ks * 8;
        uint32_t a[4][4], bb[4][2];
#pragma unroll
        for (int ma = 0; ma < 4; ma++) {
            int w = (wm * 64 + ma * 16 + lr) * KW128 + k0w + lk;
            a[ma][0] = Asm[w];            a[ma][1] = Asm[w + 8 * KW128];
            a[ma][2] = Asm[w + 4];        a[ma][3] = Asm[w + 8 * KW128 + 4];
        }
#pragma unroll
        for (int na = 0; na < 4; na++) {
            int w = (wn * 32 + na * 8 + lr) * KW128 + k0w + lk;
            bb[na][0] = Bsm[w];           bb[na][1] = Bsm[w + 4];
        }
#pragma unroll
        for (int ma = 0; ma < 4; ma++)
#pragma unroll
            for (int na = 0; na < 4; na++)
                mma16816(acc[ma][na], a[ma][0], a[ma][1], a[ma][2], a[ma][3],
                         bb[na][0], bb[na][1]);
    }

    const float* vb = vin + ((size_t)b * NC + c0) * NN + n0;
    float*       yb = y   + ((size_t)b * NC + c0) * NN + n0;
#pragma unroll
    for (int ma = 0; ma < 4; ma++) {
        int r0 = wm * 64 + ma * 16 + lr;
#pragma unroll
        for (int na = 0; na < 4; na++) {
            int c = wn * 32 + na * 8 + lk * 2;
            float2 v0 = *(const float2*)(vb + (size_t)r0 * NN + c);
            float2 v1 = *(const float2*)(vb + (size_t)(r0 + 8) * NN + c);
            *(float2*)(yb + (size_t)r0 * NN + c)       = make_float2(acc[ma][na][0] + v0.x, acc[ma][na][1] + v0.y);
            *(float2*)(yb + (size_t)(r0 + 8) * NN + c) = make_float2(acc[ma][na][2] + v1.x, acc[ma][na][3] + v1.y);
        }
    }
}

// ================================================================================
extern "C" void kernel_launch(void* const* d_in, const int* in_sizes, int n_in,
                              void* d_out, int out_size)
{
    const float* q  = (const float*)d_in[0];
    const float* k  = (const float*)d_in[1];
    const float* v  = (const float*)d_in[2];
    const float* Wt = (const float*)d_in[3];
    const float* Wp = (const float*)d_in[4];
    const float* Wg = (const float*)d_in[5];
    const float* Wo = (const float*)d_in[6];
    float* y = (float*)d_out;

    cudaFuncSetAttribute(proj_kernel,  cudaFuncAttributeMaxDynamicSharedMemorySize, 2 * TILE128 * 4);
    cudaFuncSetAttribute(s_kernel,     cudaFuncAttributeMaxDynamicSharedMemorySize, 3 * TILE128 * 4);
    cudaFuncSetAttribute(pv_kernel,    cudaFuncAttributeMaxDynamicSharedMemorySize, PV_SMEM);
    cudaFuncSetAttribute(final_kernel, cudaFuncAttributeMaxDynamicSharedMemorySize, 2 * TILE128 * 4);

    void* sumAddr = nullptr;
    cudaGetSymbolAddress(&sumAddr, g_sum);
    cudaMemsetAsync(sumAddr, 0, NB * NN * sizeof(float));

    proj_kernel  <<<dim3(3, NN / 128, NB), 256, 2 * TILE128 * 4>>>(q, k, v, Wt, Wp, Wg);
    s_kernel     <<<dim3(NN / 128, NB), 256, 3 * TILE128 * 4>>>();
    vscale_kernel<<<dim3((NB * ND * NN / 8) / 256), 256>>>();
    pv_kernel    <<<dim3(NN / 128, NB), 256, PV_SMEM>>>();
    final_kernel <<<dim3(NN / 128, NC / 128, NB), 256, 2 * TILE128 * 4>>>(v, Wo, y);
}